// round 1
// baseline (speedup 1.0000x reference)
#include <cuda_runtime.h>
#include <cuda_bf16.h>
#include <cstdint>

// Inverse 2x2 Haar synthesis.
// Input  x: [B=8, 4*C=256, H=256, W=256] fp32  (subband-major: k*C + c)
// Output o: [B=8, C=64, 2H=512, 2W=512] fp32
//
// o[b,c,2h+0,2w+0] = (ll+lh+hl+hh)/4
// o[b,c,2h+0,2w+1] = (ll+lh-hl-hh)/4
// o[b,c,2h+1,2w+0] = (ll-lh+hl-hh)/4
// o[b,c,2h+1,2w+1] = (ll-lh-hl+hh)/4
//
// Thread granularity: one float4 of input w-positions per subband
// -> 4 float4 loads, 4 float4 stores, all coalesced.

static constexpr int B  = 8;
static constexpr int C  = 64;
static constexpr int H  = 256;
static constexpr int W  = 256;
static constexpr int W4 = W / 4;            // 64 float4 per input row
static constexpr int OW4 = (2 * W) / 4;     // 128 float4 per output row

// float4 strides
static constexpr int IN_CH_STRIDE   = H * W4;            // per (k*C+c) channel: 256*64
static constexpr int IN_B_STRIDE    = 4 * C * IN_CH_STRIDE;
static constexpr int IN_K_STRIDE    = C * IN_CH_STRIDE;  // subband stride
static constexpr int OUT_CH_STRIDE  = 2 * H * OW4;       // 512*128
static constexpr int OUT_B_STRIDE   = C * OUT_CH_STRIDE;

static constexpr long long N_THREADS_TOTAL = (long long)B * C * H * W4; // 8,388,608

__global__ __launch_bounds__(256)
void iwt_kernel(const float4* __restrict__ in, float4* __restrict__ out)
{
    unsigned i = blockIdx.x * blockDim.x + threadIdx.x;   // < 2^23, fits unsigned
    // decompose: i = ((b*C + c)*H + h)*W4 + w4
    unsigned w4 = i & (W4 - 1);
    unsigned t  = i >> 6;            // /W4
    unsigned h  = t & (H - 1);
    unsigned t2 = t >> 8;            // /H
    unsigned c  = t2 & (C - 1);
    unsigned b  = t2 >> 6;           // /C

    unsigned in_base = b * IN_B_STRIDE + c * IN_CH_STRIDE + h * W4 + w4;

    float4 ll = in[in_base + 0 * IN_K_STRIDE];
    float4 lh = in[in_base + 1 * IN_K_STRIDE];
    float4 hl = in[in_base + 2 * IN_K_STRIDE];
    float4 hh = in[in_base + 3 * IN_K_STRIDE];

    // per-lane butterflies
    float s1x = ll.x + lh.x, s2x = hl.x + hh.x, d1x = ll.x - lh.x, d2x = hl.x - hh.x;
    float s1y = ll.y + lh.y, s2y = hl.y + hh.y, d1y = ll.y - lh.y, d2y = hl.y - hh.y;
    float s1z = ll.z + lh.z, s2z = hl.z + hh.z, d1z = ll.z - lh.z, d2z = hl.z - hh.z;
    float s1w = ll.w + lh.w, s2w = hl.w + hh.w, d1w = ll.w - lh.w, d2w = hl.w - hh.w;

    const float q = 0.25f;

    // row y = 2h   : interleave (o00, o01) per lane
    float4 r0a = make_float4((s1x + s2x) * q, (s1x - s2x) * q,
                             (s1y + s2y) * q, (s1y - s2y) * q);
    float4 r0b = make_float4((s1z + s2z) * q, (s1z - s2z) * q,
                             (s1w + s2w) * q, (s1w - s2w) * q);
    // row y = 2h+1 : interleave (o10, o11) per lane
    float4 r1a = make_float4((d1x + d2x) * q, (d1x - d2x) * q,
                             (d1y + d2y) * q, (d1y - d2y) * q);
    float4 r1b = make_float4((d1z + d2z) * q, (d1z - d2z) * q,
                             (d1w + d2w) * q, (d1w - d2w) * q);

    unsigned out_base = b * OUT_B_STRIDE + c * OUT_CH_STRIDE
                      + (2 * h) * OW4 + 2 * w4;

    out[out_base + 0]       = r0a;
    out[out_base + 1]       = r0b;
    out[out_base + OW4 + 0] = r1a;
    out[out_base + OW4 + 1] = r1b;
}

extern "C" void kernel_launch(void* const* d_in, const int* in_sizes, int n_in,
                              void* d_out, int out_size)
{
    const float4* in  = (const float4*)d_in[0];
    float4*       out = (float4*)d_out;

    const int threads = 256;
    const long long total = N_THREADS_TOTAL;
    const int blocks = (int)(total / threads);   // 32768

    iwt_kernel<<<blocks, threads>>>(in, out);
}

// round 2
// speedup vs baseline: 1.0405x; 1.0405x over previous
#include <cuda_runtime.h>
#include <cuda_bf16.h>
#include <cstdint>

// Inverse 2x2 Haar synthesis, output-centric mapping.
// Input  x: [B=8, 4*C=256, H=256, W=256] fp32  (subband-major: k*C + c)
// Output o: [B=8, C=64, 2H=512, 2W=512] fp32
//
// Each thread produces one output float4 per output-row-pair:
//   output float4 at row-index j covers output cols 4j..4j+3,
//   sourced from input cols 2j, 2j+1 = one input float2 at index j.
// -> loads:  4 x LDG.64  fully coalesced (256B/warp)
// -> stores: 2 x STG.128 fully coalesced (512B/warp, full sectors)

static constexpr int B   = 8;
static constexpr int C   = 64;
static constexpr int H   = 256;
static constexpr int W   = 256;
static constexpr int W2  = W / 2;          // 128 float2 per input row
static constexpr int OW4 = (2 * W) / 4;    // 128 float4 per output row

// float2 strides (input)
static constexpr int IN_CH_STRIDE2 = H * W2;                 // 32768
static constexpr int IN_K_STRIDE2  = C * IN_CH_STRIDE2;      // 2,097,152
static constexpr int IN_B_STRIDE2  = 4 * IN_K_STRIDE2;

// float4 strides (output)
static constexpr int OUT_CH_STRIDE4 = 2 * H * OW4;           // 65536
static constexpr int OUT_B_STRIDE4  = C * OUT_CH_STRIDE4;

static constexpr unsigned N_THREADS_TOTAL = (unsigned)B * C * H * OW4;  // 16,777,216

__device__ __forceinline__ float2 ldcs2(const float2* p) {
    float2 v;
    asm volatile("ld.global.cs.v2.f32 {%0, %1}, [%2];"
                 : "=f"(v.x), "=f"(v.y) : "l"(p));
    return v;
}

__device__ __forceinline__ void stcs4(float4* p, float4 v) {
    asm volatile("st.global.cs.v4.f32 [%0], {%1, %2, %3, %4};"
                 :: "l"(p), "f"(v.x), "f"(v.y), "f"(v.z), "f"(v.w));
}

__global__ __launch_bounds__(256)
void iwt_kernel(const float2* __restrict__ in, float4* __restrict__ out)
{
    unsigned i = blockIdx.x * blockDim.x + threadIdx.x;   // < 2^24
    // decompose: i = ((b*C + c)*H + h)*OW4 + j
    unsigned j  = i & (OW4 - 1);
    unsigned t  = i >> 7;
    unsigned h  = t & (H - 1);
    unsigned t2 = t >> 8;
    unsigned c  = t2 & (C - 1);
    unsigned b  = t2 >> 6;

    unsigned in_base = b * IN_B_STRIDE2 + c * IN_CH_STRIDE2 + h * W2 + j;

    float2 ll = ldcs2(in + in_base + 0 * IN_K_STRIDE2);
    float2 lh = ldcs2(in + in_base + 1 * IN_K_STRIDE2);
    float2 hl = ldcs2(in + in_base + 2 * IN_K_STRIDE2);
    float2 hh = ldcs2(in + in_base + 3 * IN_K_STRIDE2);

    // butterflies per input column (x = col 2j, y = col 2j+1)
    float s1x = ll.x + lh.x, s2x = hl.x + hh.x;
    float d1x = ll.x - lh.x, d2x = hl.x - hh.x;
    float s1y = ll.y + lh.y, s2y = hl.y + hh.y;
    float d1y = ll.y - lh.y, d2y = hl.y - hh.y;

    const float q = 0.25f;

    // row 2h   : [o00(2j), o01(2j), o00(2j+1), o01(2j+1)]
    float4 r0 = make_float4((s1x + s2x) * q, (s1x - s2x) * q,
                            (s1y + s2y) * q, (s1y - s2y) * q);
    // row 2h+1 : [o10(2j), o11(2j), o10(2j+1), o11(2j+1)]
    float4 r1 = make_float4((d1x + d2x) * q, (d1x - d2x) * q,
                            (d1y + d2y) * q, (d1y - d2y) * q);

    unsigned out_base = b * OUT_B_STRIDE4 + c * OUT_CH_STRIDE4
                      + (2 * h) * OW4 + j;

    stcs4(out + out_base,       r0);
    stcs4(out + out_base + OW4, r1);
}

extern "C" void kernel_launch(void* const* d_in, const int* in_sizes, int n_in,
                              void* d_out, int out_size)
{
    const float2* in  = (const float2*)d_in[0];
    float4*       out = (float4*)d_out;

    const int threads = 256;
    const int blocks  = (int)(N_THREADS_TOTAL / threads);   // 65536

    iwt_kernel<<<blocks, threads>>>(in, out);
}